// round 14
// baseline (speedup 1.0000x reference)
#include <cuda_runtime.h>
#include <cfloat>

#define B   32
#define C   512
#define H   56
#define W   56
#define HW  (H * W)          // 3136
#define HW4 (HW / 4)         // 784
#define KD  768
#define NTOT ((size_t)B * C * HW)

// pooling block geometry (R6-proven): 16 hw4-cols x 16 channel-chunks
#define PTX 16
#define PTY 16
#define PCC (C / PTY)        // 32 channels per thread
#define PBLK_PER_B (HW4 / PTX)   // 49

// conv tiling: 8 output rows per block
#define CROWS 8
#define CTH   (CROWS + 6)    // 14
#define CTW   64

// mul: channels per thread
#define MCH 8
#define MCHUNKS (C / MCH)    // 64 channel-groups

// Scratch (alloc-free rule: __device__ globals)
__device__ float g_pooled[B * 2 * HW];
__device__ float g_scale[B * HW];

// ---------------------------------------------------------------------------
// Kernel 1: fused channel max+mean pooling (R6-proven geometry, untouched).
// ---------------------------------------------------------------------------
__global__ void __launch_bounds__(PTX * PTY)
pool_kernel(const float4* __restrict__ x4) {
    int tx = threadIdx.x & (PTX - 1);
    int ty = threadIdx.x >> 4;
    int b   = blockIdx.y;
    int hw4 = blockIdx.x * PTX + tx;

    const float4* p = x4 + (size_t)b * C * HW4
                         + (size_t)ty * PCC * HW4 + hw4;
    float4 v0 = __ldg(p);
    float4 mx = v0;
    float4 sm = v0;
#pragma unroll
    for (int c = 1; c < PCC; ++c) {
        float4 v = __ldg(p + (size_t)c * HW4);
        mx.x = fmaxf(mx.x, v.x); mx.y = fmaxf(mx.y, v.y);
        mx.z = fmaxf(mx.z, v.z); mx.w = fmaxf(mx.w, v.w);
        sm.x += v.x; sm.y += v.y; sm.z += v.z; sm.w += v.w;
    }

    __shared__ float4 smax[PTY][PTX];
    __shared__ float4 ssum[PTY][PTX];
    smax[ty][tx] = mx;
    ssum[ty][tx] = sm;
    __syncthreads();

#pragma unroll
    for (int s = PTY / 2; s > 0; s >>= 1) {
        if (ty < s) {
            float4 m = smax[ty + s][tx];
            float4 q = ssum[ty + s][tx];
            mx.x = fmaxf(mx.x, m.x); mx.y = fmaxf(mx.y, m.y);
            mx.z = fmaxf(mx.z, m.z); mx.w = fmaxf(mx.w, m.w);
            sm.x += q.x; sm.y += q.y; sm.z += q.z; sm.w += q.w;
            smax[ty][tx] = mx;
            ssum[ty][tx] = sm;
        }
        __syncthreads();
    }

    if (ty == 0) {
        const float inv = 1.0f / C;
        sm.x *= inv; sm.y *= inv; sm.z *= inv; sm.w *= inv;
        float4* pool4 = reinterpret_cast<float4*>(g_pooled);
        pool4[(b * 2 * HW) / 4 + hw4]      = mx;
        pool4[(b * 2 * HW + HW) / 4 + hw4] = sm;
    }
}

// ---------------------------------------------------------------------------
// Kernel 2: smem-tiled 7x7 conv + sigmoid + keyword bias (CROWS=8).
// ---------------------------------------------------------------------------
__global__ void conv_kernel(const float* __restrict__ conv_w,
                            const float* __restrict__ conv_b,
                            const float* __restrict__ keyword,
                            const float* __restrict__ proj_w,
                            const float* __restrict__ proj_b) {
    __shared__ float tile[2][CTH][CTW];   // 7 KB
    __shared__ float wts[98];
    __shared__ float wsum[8];
    __shared__ float sbias;

    int b  = blockIdx.y;
    int r0 = blockIdx.x * CROWS;
    int tid = threadIdx.x;

    if (tid < 98) wts[tid] = __ldg(conv_w + tid);

    {
        float s = 0.0f;
        const float* kb = keyword + b * KD;
#pragma unroll
        for (int k = tid; k < KD; k += 256)
            s += __ldg(kb + k) * __ldg(proj_w + k);
#pragma unroll
        for (int off = 16; off > 0; off >>= 1)
            s += __shfl_down_sync(0xFFFFFFFFu, s, off);
        if ((tid & 31) == 0) wsum[tid >> 5] = s;
    }

    const float* pb = g_pooled + b * 2 * HW;
    for (int i = tid; i < 2 * CTH * CTW; i += 256) {
        int ci = i / (CTH * CTW);
        int rr = (i / CTW) % CTH;
        int cc = i % CTW;
        int hh = r0 + rr - 3;
        int ww = cc - 3;
        float v = 0.0f;
        if ((unsigned)hh < (unsigned)H && (unsigned)ww < (unsigned)W)
            v = pb[ci * HW + hh * W + ww];
        tile[ci][rr][cc] = v;
    }
    __syncthreads();

    if (tid == 0) {
        float t = 0.0f;
#pragma unroll
        for (int i = 0; i < 8; ++i) t += wsum[i];
        sbias = t + __ldg(proj_b) + __ldg(conv_b);
    }
    __syncthreads();

#pragma unroll
    for (int o = tid; o < CROWS * W; o += 256) {
        int r = o / W;
        int w = o - r * W;
        float acc = sbias;
#pragma unroll
        for (int ci = 0; ci < 2; ++ci) {
#pragma unroll
            for (int kh = 0; kh < 7; ++kh) {
#pragma unroll
                for (int kw = 0; kw < 7; ++kw) {
                    acc += tile[ci][r + kh][w + kw] * wts[ci * 49 + kh * 7 + kw];
                }
            }
        }
        g_scale[b * HW + (r0 + r) * W + w] = 1.0f / (1.0f + __expf(-acc));
    }
}

// ---------------------------------------------------------------------------
// Kernel 3: out = x * scale. Each thread owns one (b, hw4), loads its scale
// float4 ONCE, and gates MCH=8 channels (x strided by HW4 — warp-contiguous
// 512B segments, same pattern pool uses). Scale LTS traffic drops ~8x.
// ---------------------------------------------------------------------------
__global__ void __launch_bounds__(256)
mul_kernel(const float4* __restrict__ x4, float4* __restrict__ out4) {
    // flattened work: (b, cgroup, hw4)
    int t = blockIdx.x * blockDim.x + threadIdx.x;
    const int NW = B * MCHUNKS * HW4;     // 32*64*784 = 1,605,632 threads
    if (t >= NW) return;

    int hw4 = t % HW4;
    int r   = t / HW4;
    int cg  = r % MCHUNKS;
    int b   = r / MCHUNKS;

    float4 s = __ldg(reinterpret_cast<const float4*>(g_scale) + b * HW4 + hw4);

    const size_t base = (size_t)(b * C + cg * MCH) * HW4 + hw4;
#pragma unroll
    for (int c = 0; c < MCH; ++c) {
        size_t g = base + (size_t)c * HW4;
        float4 v = __ldcs(x4 + g);
        v.x *= s.x; v.y *= s.y; v.z *= s.z; v.w *= s.w;
        __stcs(out4 + g, v);
    }
}

// ---------------------------------------------------------------------------
extern "C" void kernel_launch(void* const* d_in, const int* in_sizes, int n_in,
                              void* d_out, int out_size) {
    const float* x       = (const float*)d_in[0];
    const float* keyword = (const float*)d_in[1];
    const float* conv_w  = (const float*)d_in[2];
    const float* conv_b  = (const float*)d_in[3];
    const float* proj_w  = (const float*)d_in[4];
    const float* proj_b  = (const float*)d_in[5];
    float* out = (float*)d_out;

    {
        dim3 grid(PBLK_PER_B, B);        // 49 x 32
        pool_kernel<<<grid, PTX * PTY>>>((const float4*)x);
    }
    {
        dim3 grid(H / CROWS, B);         // 7 x 32 = 224
        conv_kernel<<<grid, 256>>>(conv_w, conv_b, keyword, proj_w, proj_b);
    }
    {
        int nw = B * MCHUNKS * HW4;
        mul_kernel<<<(nw + 255) / 256, 256>>>((const float4*)x, (float4*)out);
    }
}

// round 15
// speedup vs baseline: 1.0069x; 1.0069x over previous
#include <cuda_runtime.h>
#include <cfloat>

#define B   32
#define C   512
#define H   56
#define W   56
#define HW  (H * W)          // 3136
#define HW4 (HW / 4)         // 784
#define KD  768
#define NTOT ((size_t)B * C * HW)

// pooling block geometry (R7 best-run config): 16 hw4-cols x 8 chunks, 128 thr
#define PTX 16
#define PTY 8
#define PCC (C / PTY)        // 64 channels per thread
#define PBLK_PER_B (HW4 / PTX)   // 49

// conv tiling (R6-proven): 4 output rows per block
#define CROWS 4
#define CTH   (CROWS + 6)
#define CTW   64

// Scratch (alloc-free rule: __device__ globals)
__device__ float g_pooled[B * 2 * HW];
__device__ float g_scale[B * HW];

// ---------------------------------------------------------------------------
// Kernel 1: fused channel max+mean pooling (exact R7 body).
// ---------------------------------------------------------------------------
__global__ void __launch_bounds__(PTX * PTY)
pool_kernel(const float4* __restrict__ x4) {
    int tx = threadIdx.x & (PTX - 1);
    int ty = threadIdx.x >> 4;            // 0..7
    int b   = blockIdx.y;
    int hw4 = blockIdx.x * PTX + tx;

    const float4* p = x4 + (size_t)b * C * HW4
                         + (size_t)ty * PCC * HW4 + hw4;
    float4 v0 = __ldg(p);
    float4 mx = v0;
    float4 sm = v0;
#pragma unroll 16
    for (int c = 1; c < PCC; ++c) {
        float4 v = __ldg(p + (size_t)c * HW4);
        mx.x = fmaxf(mx.x, v.x); mx.y = fmaxf(mx.y, v.y);
        mx.z = fmaxf(mx.z, v.z); mx.w = fmaxf(mx.w, v.w);
        sm.x += v.x; sm.y += v.y; sm.z += v.z; sm.w += v.w;
    }

    __shared__ float4 smax[PTY][PTX];
    __shared__ float4 ssum[PTY][PTX];
    smax[ty][tx] = mx;
    ssum[ty][tx] = sm;
    __syncthreads();

#pragma unroll
    for (int s = PTY / 2; s > 0; s >>= 1) {
        if (ty < s) {
            float4 m = smax[ty + s][tx];
            float4 q = ssum[ty + s][tx];
            mx.x = fmaxf(mx.x, m.x); mx.y = fmaxf(mx.y, m.y);
            mx.z = fmaxf(mx.z, m.z); mx.w = fmaxf(mx.w, m.w);
            sm.x += q.x; sm.y += q.y; sm.z += q.z; sm.w += q.w;
            smax[ty][tx] = mx;
            ssum[ty][tx] = sm;
        }
        __syncthreads();
    }

    if (ty == 0) {
        const float inv = 1.0f / C;
        sm.x *= inv; sm.y *= inv; sm.z *= inv; sm.w *= inv;
        float4* pool4 = reinterpret_cast<float4*>(g_pooled);
        pool4[(b * 2 * HW) / 4 + hw4]      = mx;
        pool4[(b * 2 * HW + HW) / 4 + hw4] = sm;
    }
}

// ---------------------------------------------------------------------------
// Kernel 2: smem-tiled 7x7 conv + sigmoid + keyword bias (exact R6 body).
// grid = (14, 32), 256 threads.
// ---------------------------------------------------------------------------
__global__ void conv_kernel(const float* __restrict__ conv_w,
                            const float* __restrict__ conv_b,
                            const float* __restrict__ keyword,
                            const float* __restrict__ proj_w,
                            const float* __restrict__ proj_b) {
    __shared__ float tile[2][CTH][CTW];   // 5 KB
    __shared__ float wts[98];
    __shared__ float wsum[8];
    __shared__ float sbias;

    int b  = blockIdx.y;
    int r0 = blockIdx.x * CROWS;
    int tid = threadIdx.x;

    if (tid < 98) wts[tid] = conv_w[tid];

    // keyword bias: dot(keyword[b], proj_w) + proj_b + conv_b
    {
        float s = 0.0f;
        const float* kb = keyword + b * KD;
#pragma unroll
        for (int k = tid; k < KD; k += 256)
            s += kb[k] * proj_w[k];
#pragma unroll
        for (int off = 16; off > 0; off >>= 1)
            s += __shfl_down_sync(0xFFFFFFFFu, s, off);
        if ((tid & 31) == 0) wsum[tid >> 5] = s;
    }

    // cooperative pooled-tile load
    const float* pb = g_pooled + b * 2 * HW;
    for (int i = tid; i < 2 * CTH * CTW; i += 256) {
        int ci = i / (CTH * CTW);
        int rr = (i / CTW) % CTH;
        int cc = i % CTW;
        int hh = r0 + rr - 3;
        int ww = cc - 3;
        float v = 0.0f;
        if ((unsigned)hh < (unsigned)H && (unsigned)ww < (unsigned)W)
            v = pb[ci * HW + hh * W + ww];
        tile[ci][rr][cc] = v;
    }
    __syncthreads();

    if (tid == 0) {
        float t = 0.0f;
#pragma unroll
        for (int i = 0; i < 8; ++i) t += wsum[i];
        sbias = t + proj_b[0] + conv_b[0];
    }
    __syncthreads();

    if (tid < CROWS * W) {
        int r = tid / W;
        int w = tid - r * W;
        float acc = sbias;
#pragma unroll
        for (int ci = 0; ci < 2; ++ci) {
#pragma unroll
            for (int kh = 0; kh < 7; ++kh) {
#pragma unroll
                for (int kw = 0; kw < 7; ++kw) {
                    acc += tile[ci][r + kh][w + kw] * wts[ci * 49 + kh * 7 + kw];
                }
            }
        }
        g_scale[b * HW + (r0 + r) * W + w] = 1.0f / (1.0f + __expf(-acc));
    }
}

// ---------------------------------------------------------------------------
// Kernel 3: out = x * scale (R1 plain body — best measured mul at 60.6us).
// ---------------------------------------------------------------------------
__global__ void mul_kernel(const float4* __restrict__ x4,
                           float4* __restrict__ out4) {
    const int CHW4 = C * HW4;
    int i = blockIdx.x * blockDim.x + threadIdx.x;
    if (i >= (int)(NTOT / 4)) return;
    int b   = i / CHW4;
    int rem = i - b * CHW4;
    int hw4 = rem % HW4;

    float4 s = reinterpret_cast<const float4*>(g_scale)[b * HW4 + hw4];
    float4 v = x4[i];
    v.x *= s.x; v.y *= s.y; v.z *= s.z; v.w *= s.w;
    out4[i] = v;
}

// ---------------------------------------------------------------------------
extern "C" void kernel_launch(void* const* d_in, const int* in_sizes, int n_in,
                              void* d_out, int out_size) {
    const float* x       = (const float*)d_in[0];
    const float* keyword = (const float*)d_in[1];
    const float* conv_w  = (const float*)d_in[2];
    const float* conv_b  = (const float*)d_in[3];
    const float* proj_w  = (const float*)d_in[4];
    const float* proj_b  = (const float*)d_in[5];
    float* out = (float*)d_out;

    {
        dim3 grid(PBLK_PER_B, B);        // 49 x 32
        pool_kernel<<<grid, PTX * PTY>>>((const float4*)x);
    }
    {
        dim3 grid(H / CROWS, B);         // 14 x 32
        conv_kernel<<<grid, 256>>>(conv_w, conv_b, keyword, proj_w, proj_b);
    }
    {
        int n4 = (int)(NTOT / 4);
        mul_kernel<<<(n4 + 255) / 256, 256>>>((const float4*)x, (float4*)out);
    }
}

// round 16
// speedup vs baseline: 1.0413x; 1.0341x over previous
#include <cuda_runtime.h>
#include <cfloat>

#define B   32
#define C   512
#define H   56
#define W   56
#define HW  (H * W)          // 3136
#define HW4 (HW / 4)         // 784
#define KD  768
#define NTOT ((size_t)B * C * HW)

// pooling block geometry: 16 hw4-columns x 8 channel-chunks, 128 threads
#define PTX 16
#define PTY 8
#define PCC (C / PTY)        // 64 channels per thread
#define PBLK_PER_B (HW4 / PTX)   // 49

// conv tiling
#define CROWS 4
#define CTH   (CROWS + 6)
#define CTW   64

// Scratch (alloc-free rule: __device__ globals)
__device__ float g_pooled[B * 2 * HW];
__device__ float g_scale[B * HW];

// ---------------------------------------------------------------------------
// Kernel 1: fused channel max+mean pooling.
// 128-thread blocks, 64-deep MLP per thread, 3-stage smem reduce.
// ---------------------------------------------------------------------------
__global__ void __launch_bounds__(PTX * PTY)
pool_kernel(const float4* __restrict__ x4) {
    int tx = threadIdx.x & (PTX - 1);
    int ty = threadIdx.x >> 4;            // 0..7
    int b   = blockIdx.y;
    int hw4 = blockIdx.x * PTX + tx;

    const float4* p = x4 + (size_t)b * C * HW4
                         + (size_t)ty * PCC * HW4 + hw4;
    float4 v0 = __ldg(p);
    float4 mx = v0;
    float4 sm = v0;
#pragma unroll 16
    for (int c = 1; c < PCC; ++c) {
        float4 v = __ldg(p + (size_t)c * HW4);
        mx.x = fmaxf(mx.x, v.x); mx.y = fmaxf(mx.y, v.y);
        mx.z = fmaxf(mx.z, v.z); mx.w = fmaxf(mx.w, v.w);
        sm.x += v.x; sm.y += v.y; sm.z += v.z; sm.w += v.w;
    }

    __shared__ float4 smax[PTY][PTX];
    __shared__ float4 ssum[PTY][PTX];
    smax[ty][tx] = mx;
    ssum[ty][tx] = sm;
    __syncthreads();

#pragma unroll
    for (int s = PTY / 2; s > 0; s >>= 1) {
        if (ty < s) {
            float4 m = smax[ty + s][tx];
            float4 q = ssum[ty + s][tx];
            mx.x = fmaxf(mx.x, m.x); mx.y = fmaxf(mx.y, m.y);
            mx.z = fmaxf(mx.z, m.z); mx.w = fmaxf(mx.w, m.w);
            sm.x += q.x; sm.y += q.y; sm.z += q.z; sm.w += q.w;
            smax[ty][tx] = mx;
            ssum[ty][tx] = sm;
        }
        __syncthreads();
    }

    if (ty == 0) {
        const float inv = 1.0f / C;
        sm.x *= inv; sm.y *= inv; sm.z *= inv; sm.w *= inv;
        float4* pool4 = reinterpret_cast<float4*>(g_pooled);
        pool4[(b * 2 * HW) / 4 + hw4]      = mx;
        pool4[(b * 2 * HW + HW) / 4 + hw4] = sm;
    }
}

// ---------------------------------------------------------------------------
// Kernel 2: smem-tiled 7x7 conv + sigmoid, keyword bias folded in.
// grid = (14, 32), 256 threads.
// ---------------------------------------------------------------------------
__global__ void conv_kernel(const float* __restrict__ conv_w,
                            const float* __restrict__ conv_b,
                            const float* __restrict__ keyword,
                            const float* __restrict__ proj_w,
                            const float* __restrict__ proj_b) {
    __shared__ float tile[2][CTH][CTW];   // 5 KB
    __shared__ float wts[98];
    __shared__ float wsum[8];
    __shared__ float sbias;

    int b  = blockIdx.y;
    int r0 = blockIdx.x * CROWS;
    int tid = threadIdx.x;

    if (tid < 98) wts[tid] = conv_w[tid];

    // keyword bias: dot(keyword[b], proj_w) + proj_b + conv_b
    {
        float s = 0.0f;
        const float* kb = keyword + b * KD;
#pragma unroll
        for (int k = tid; k < KD; k += 256)
            s += kb[k] * proj_w[k];
#pragma unroll
        for (int off = 16; off > 0; off >>= 1)
            s += __shfl_down_sync(0xFFFFFFFFu, s, off);
        if ((tid & 31) == 0) wsum[tid >> 5] = s;
    }

    // cooperative pooled-tile load
    const float* pb = g_pooled + b * 2 * HW;
    for (int i = tid; i < 2 * CTH * CTW; i += 256) {
        int ci = i / (CTH * CTW);
        int rr = (i / CTW) % CTH;
        int cc = i % CTW;
        int hh = r0 + rr - 3;
        int ww = cc - 3;
        float v = 0.0f;
        if ((unsigned)hh < (unsigned)H && (unsigned)ww < (unsigned)W)
            v = pb[ci * HW + hh * W + ww];
        tile[ci][rr][cc] = v;
    }
    __syncthreads();

    if (tid == 0) {
        float t = 0.0f;
#pragma unroll
        for (int i = 0; i < 8; ++i) t += wsum[i];
        sbias = t + proj_b[0] + conv_b[0];
    }
    __syncthreads();

    if (tid < CROWS * W) {
        int r = tid / W;
        int w = tid - r * W;
        float acc = sbias;
#pragma unroll
        for (int ci = 0; ci < 2; ++ci) {
#pragma unroll
            for (int kh = 0; kh < 7; ++kh) {
#pragma unroll
                for (int kw = 0; kw < 7; ++kw) {
                    acc += tile[ci][r + kh][w + kw] * wts[ci * 49 + kh * 7 + kw];
                }
            }
        }
        g_scale[b * HW + (r0 + r) * W + w] = 1.0f / (1.0f + __expf(-acc));
    }
}

// ---------------------------------------------------------------------------
// Kernel 3: out = x * scale (broadcast over C). float4 streaming.
// ---------------------------------------------------------------------------
__global__ void mul_kernel(const float4* __restrict__ x4,
                           float4* __restrict__ out4) {
    const int CHW4 = C * HW4;
    int i = blockIdx.x * blockDim.x + threadIdx.x;
    if (i >= (int)(NTOT / 4)) return;
    int b   = i / CHW4;
    int rem = i - b * CHW4;
    int hw4 = rem % HW4;

    float4 s = reinterpret_cast<const float4*>(g_scale)[b * HW4 + hw4];
    float4 v = __ldcs(x4 + i);
    v.x *= s.x; v.y *= s.y; v.z *= s.z; v.w *= s.w;
    __stcs(out4 + i, v);
}

// ---------------------------------------------------------------------------
extern "C" void kernel_launch(void* const* d_in, const int* in_sizes, int n_in,
                              void* d_out, int out_size) {
    const float* x       = (const float*)d_in[0];
    const float* keyword = (const float*)d_in[1];
    const float* conv_w  = (const float*)d_in[2];
    const float* conv_b  = (const float*)d_in[3];
    const float* proj_w  = (const float*)d_in[4];
    const float* proj_b  = (const float*)d_in[5];
    float* out = (float*)d_out;

    {
        dim3 grid(PBLK_PER_B, B);        // 49 x 32
        pool_kernel<<<grid, PTX * PTY>>>((const float4*)x);
    }
    {
        dim3 grid(H / CROWS, B);         // 14 x 32
        conv_kernel<<<grid, 256>>>(conv_w, conv_b, keyword, proj_w, proj_b);
    }
    {
        int n4 = (int)(NTOT / 4);
        mul_kernel<<<(n4 + 255) / 256, 256>>>((const float4*)x, (float4*)out);
    }
}